// round 9
// baseline (speedup 1.0000x reference)
#include <cuda_runtime.h>
#include <cuda_bf16.h>
#include <cstddef>

#define BB 8
#define NN 2048
#define NODES (BB*NN)          // 16384
#define FP 72                  // padded feature width (66 real)
#define DSZ 32
#define BM 256
#define BK 32
#define NT (NN/BK)             // 64 k-tiles
#define STAGE_E 26240          // elems/stage: Ah 10240 + Al 10240 + Xh 2880 + Xl 2880

// ---------------- scratch (device globals, no allocation) ----------------
__device__ float g_X[NODES*FP];
__device__ float g_C[NODES*FP];
__device__ float g_state[NODES*DSZ];
__device__ float g_r[NODES*DSZ];
__device__ float g_T1[2*NODES*FP];
__device__ float g_T2[2*NODES*FP];
__device__ float g_U1[2*NODES*FP];
__device__ float g_U2[2*NODES*FP];

// transposed/split dense-input planes [plane][72][2048]
__device__ __align__(16) __nv_bfloat16 g_InTh[16ull*FP*NN];
__device__ __align__(16) __nv_bfloat16 g_InTl[16ull*FP*NN];

// ---------------- helpers ----------------
__device__ __forceinline__ unsigned long long pk2(float lo, float hi){
    unsigned long long r;
    asm("mov.b64 %0, {%1,%2};" : "=l"(r) : "f"(lo), "f"(hi));
    return r;
}
__device__ __forceinline__ void fma2(unsigned long long &d, unsigned long long a, unsigned long long b){
    asm("fma.rn.f32x2 %0, %1, %2, %0;" : "+l"(d) : "l"(a), "l"(b));
}
__device__ __forceinline__ float2 upk2(unsigned long long v){
    float lo, hi;
    asm("mov.b64 {%0,%1}, %2;" : "=f"(lo), "=f"(hi) : "l"(v));
    return make_float2(lo, hi);
}
__device__ __forceinline__ float sigmoidf_(float x){ return 1.f/(1.f+__expf(-x)); }

__device__ __forceinline__ void mma_bf16(float acc[4],
    unsigned a0, unsigned a1, unsigned a2, unsigned a3, unsigned b0, unsigned b1)
{
    asm volatile("mma.sync.aligned.m16n8k16.row.col.f32.bf16.bf16.f32 "
        "{%0,%1,%2,%3},{%4,%5,%6,%7},{%8,%9},{%0,%1,%2,%3};"
        : "+f"(acc[0]), "+f"(acc[1]), "+f"(acc[2]), "+f"(acc[3])
        : "r"(a0), "r"(a1), "r"(a2), "r"(a3), "r"(b0), "r"(b1));
}
__device__ __forceinline__ void ldsm4(unsigned r[4], unsigned addr){
    asm volatile("ldmatrix.sync.aligned.m8n8.x4.shared.b16 {%0,%1,%2,%3}, [%4];"
        : "=r"(r[0]), "=r"(r[1]), "=r"(r[2]), "=r"(r[3]) : "r"(addr));
}
__device__ __forceinline__ void cvsplit(float v, __nv_bfloat16 &h, __nv_bfloat16 &l){
    h = __float2bfloat16(v);
    l = __float2bfloat16(v - __bfloat162float(h));
}
__device__ __forceinline__ unsigned smem_u32(const void* p){
    unsigned a;
    asm("{ .reg .u64 t; cvta.to.shared.u64 t, %1; cvt.u32.u64 %0, t; }" : "=r"(a) : "l"(p));
    return a;
}

// ---------------- transpose+split dense input ----------------
__global__ __launch_bounds__(256)
void splitT_kernel(const float* __restrict__ in)
{
    __shared__ float xs[64][73];
    const int tid = threadIdx.x;
    const int p = blockIdx.y;
    const int nodeBase = blockIdx.x*64;
    const float* src = in + ((size_t)p*NN + nodeBase)*FP;
    for (int i = tid; i < 64*18; i += 256){
        const int n = i/18, q = i - n*18;
        const float4 v = *(const float4*)&src[(size_t)n*FP + q*4];
        xs[n][q*4+0]=v.x; xs[n][q*4+1]=v.y; xs[n][q*4+2]=v.z; xs[n][q*4+3]=v.w;
    }
    __syncthreads();
    __nv_bfloat16* oh = g_InTh + (size_t)p*FP*NN + nodeBase;
    __nv_bfloat16* ol = g_InTl + (size_t)p*FP*NN + nodeBase;
    for (int i = tid; i < FP*64; i += 256){
        const int k = i >> 6, n = i & 63;
        __nv_bfloat16 h,l; cvsplit(xs[n][k], h, l);
        oh[(size_t)k*NN + n] = h;
        ol[(size_t)k*NN + n] = l;
    }
}

// ---------------- setup: mr/state + padded X ----------------
__global__ void setup_kernel(const float* __restrict__ xt, const float* __restrict__ s1,
                             const float* __restrict__ s2, const float* __restrict__ ge,
                             const float* __restrict__ mlp_w, const float* __restrict__ mlp_b)
{
    __shared__ float w[74*32];
    __shared__ float wb[32];
    const int tid = threadIdx.x;
    for (int i = tid; i < 74*32; i += blockDim.x) w[i] = mlp_w[i];
    if (tid < 32) wb[tid] = mlp_b[tid];
    __syncthreads();

    const int node = blockIdx.x*blockDim.x + tid;

    float in[74];
    #pragma unroll
    for (int i=0;i<2;i++)  in[i]    = xt[node*2+i];
    #pragma unroll
    for (int i=0;i<32;i++) in[2+i]  = s1[node*32+i];
    #pragma unroll
    for (int i=0;i<32;i++) in[34+i] = s2[node*32+i];
    #pragma unroll
    for (int i=0;i<8;i++)  in[66+i] = ge[node*8+i];

    float acc[32];
    #pragma unroll
    for (int o=0;o<32;o++) acc[o] = wb[o];
    for (int i=0;i<74;i++){
        float v = in[i];
        #pragma unroll
        for (int o=0;o<32;o++) acc[o] += v * w[i*32+o];
    }
    #pragma unroll
    for (int o=0;o<32;o++){
        float mr = sigmoidf_(acc[o]);
        g_state[node*32+o] = mr*in[2+o] + (1.f-mr)*in[34+o];
    }

    float* X = g_X + (size_t)node*FP;
    X[0]=in[0]; X[1]=in[1];
    #pragma unroll
    for (int i=0;i<32;i++){ X[2+i]=in[2+i]; X[34+i]=in[34+i]; }
    #pragma unroll
    for (int i=66;i<FP;i++) X[i]=0.f;
}

// ---------------- big GEMM v4: BM=256, register-staged fp32 A, 2-stage ----------------
// stage layout (bf16 elems): Ah[256][40]@0, Al@10240, Xh[72][40]@20480, Xl@23360
__global__ __launch_bounds__(512, 1)
void mma_gemm4(const float* __restrict__ Abase,
               float* __restrict__ Outbase, const float* __restrict__ Subbase,
               int inPerSupport, int combo)
{
    extern __shared__ __align__(16) __nv_bfloat16 sm2[];
    const unsigned smBase = smem_u32(sm2);

    const int b = blockIdx.y, s = blockIdx.z;
    const int sb = s*BB + b;
    const int ip = inPerSupport ? sb : b;
    const float* A = Abase + (size_t)sb*NN*NN;
    const __nv_bfloat16* Xh_g = g_InTh + (size_t)ip*FP*NN;
    const __nv_bfloat16* Xl_g = g_InTl + (size_t)ip*FP*NN;
    float* Out = Outbase + (size_t)sb*NN*FP;

    const int tid = threadIdx.x;
    const int warp = tid >> 5, lane = tid & 31;
    const int gid = lane >> 2, tig = lane & 3;
    const int rowBase = blockIdx.x * BM;

    // ---- per-thread A-tile map: 2048 float4-chunks, 4 per thread ----
    const float* aPtr[4];
    unsigned aOffS[4];
    #pragma unroll
    for (int i=0;i<4;i++){
        const int c = tid + i*512;
        const int row = c >> 3, q = c & 7;
        aPtr[i]  = A + (size_t)(rowBase + row)*NN + q*4;
        aOffS[i] = row*40 + q*4;
    }

    // ---- per-thread X cp.async map: 576 16B-chunks ----
    const __nv_bfloat16* xPtr[2];
    unsigned xOffS[2];
    bool xVal[2];
    #pragma unroll
    for (int e=0;e<2;e++){
        const int c = tid + e*512;
        xVal[e] = (c < 576);
        const int cc = (c < 288) ? c : c - 288;
        const int plane = (c < 288) ? 0 : 1;
        const int r = cc >> 2, q = cc & 3;
        xPtr[e]  = (plane ? Xl_g : Xh_g) + (size_t)r*NN + q*8;
        xOffS[e] = 20480 + plane*2880 + r*40 + q*8;
    }

    #define ISSUE_X(SOFF, K0) do { \
        _Pragma("unroll") \
        for (int e=0;e<2;e++) if (xVal[e]){ \
            const unsigned dst = smBase + ((SOFF) + xOffS[e])*2; \
            asm volatile("cp.async.cg.shared.global [%0], [%1], 16;" :: "r"(dst), "l"(xPtr[e] + (K0))); \
        } \
        asm volatile("cp.async.commit_group;"); \
    } while(0)

    #define LDG_A(REGS, K0) do { \
        _Pragma("unroll") \
        for (int i=0;i<4;i++) REGS[i] = *(const float4*)(aPtr[i] + (K0)); \
    } while(0)

    #define STS_A(REGS, SOFF) do { \
        _Pragma("unroll") \
        for (int i=0;i<4;i++){ \
            __nv_bfloat16 h0,l0,h1,l1,h2,l2,h3,l3; \
            cvsplit(REGS[i].x,h0,l0); cvsplit(REGS[i].y,h1,l1); \
            cvsplit(REGS[i].z,h2,l2); cvsplit(REGS[i].w,h3,l3); \
            uint2 hv, lv; \
            ((__nv_bfloat162*)&hv)[0] = __halves2bfloat162(h0,h1); \
            ((__nv_bfloat162*)&hv)[1] = __halves2bfloat162(h2,h3); \
            ((__nv_bfloat162*)&lv)[0] = __halves2bfloat162(l0,l1); \
            ((__nv_bfloat162*)&lv)[1] = __halves2bfloat162(l2,l3); \
            *(uint2*)(sm2 + (SOFF) + aOffS[i])         = hv; \
            *(uint2*)(sm2 + (SOFF) + 10240 + aOffS[i]) = lv; \
        } \
    } while(0)

    float acc[9][4];
    #pragma unroll
    for (int j=0;j<9;j++)
        #pragma unroll
        for (int q=0;q<4;q++) acc[j][q] = 0.f;

    const unsigned aStat = (unsigned)((warp*16 + (lane&15))*40 + (lane>>4)*8);
    const unsigned bStat = (unsigned)((lane&7)*40 + (lane>>3)*8);

    float4 rA[2][4];

    // ---- prologue ----
    LDG_A(rA[0], 0);                 // A tile 0
    ISSUE_X(0, 0);                   // X tile 0 -> stage 0
    LDG_A(rA[1], BK);                // A tile 1 (in flight during convert)
    STS_A(rA[0], 0);                 // convert A0 -> stage 0
    asm volatile("cp.async.wait_group 0;");
    __syncthreads();
    // rA[1] holds A(1); loop invariant: at entry of tile t, rA[(t+1)&1] holds A(t+1)

    for (int t = 0; t < NT; t++){
        const unsigned sOff  = (unsigned)((t & 1) * STAGE_E);
        const unsigned sOffN = (unsigned)(((t+1) & 1) * STAGE_E);
        const int rN = (t+1) & 1;    // regs holding A(t+1)
        const int rF = t & 1;        // regs free for A(t+2)

        if (t + 2 < NT) LDG_A(rA[rF], (t+2)*BK);
        if (t + 1 < NT) ISSUE_X(sOffN, (t+1)*BK);

        // A fragments for tile t
        unsigned AH[2][4], AL[2][4];
        ldsm4(AH[0], smBase + (sOff + aStat)*2);
        ldsm4(AH[1], smBase + (sOff + aStat + 16)*2);
        ldsm4(AL[0], smBase + (sOff + 10240 + aStat)*2);
        ldsm4(AL[1], smBase + (sOff + 10240 + aStat + 16)*2);

        // convert A(t+1) into the other stage (independent of compute below)
        if (t + 1 < NT) STS_A(rA[rN], sOffN);

        unsigned BH[2][4], BL[2][4];
        ldsm4(BH[0], smBase + (sOff + 20480 + bStat)*2);
        ldsm4(BL[0], smBase + (sOff + 23360 + bStat)*2);
        #pragma unroll
        for (int j=0;j<9;j++){
            const int pc = j & 1, pn = pc ^ 1;
            if (j < 8){
                ldsm4(BH[pn], smBase + (sOff + 20480 + (j+1)*320 + bStat)*2);
                ldsm4(BL[pn], smBase + (sOff + 23360 + (j+1)*320 + bStat)*2);
            }
            mma_bf16(acc[j], AH[0][0],AH[0][1],AH[0][2],AH[0][3], BH[pc][0],BH[pc][1]);
            mma_bf16(acc[j], AH[0][0],AH[0][1],AH[0][2],AH[0][3], BL[pc][0],BL[pc][1]);
            mma_bf16(acc[j], AL[0][0],AL[0][1],AL[0][2],AL[0][3], BH[pc][0],BH[pc][1]);
            mma_bf16(acc[j], AH[1][0],AH[1][1],AH[1][2],AH[1][3], BH[pc][2],BH[pc][3]);
            mma_bf16(acc[j], AH[1][0],AH[1][1],AH[1][2],AH[1][3], BL[pc][2],BL[pc][3]);
            mma_bf16(acc[j], AL[1][0],AL[1][1],AL[1][2],AL[1][3], BH[pc][2],BH[pc][3]);
        }

        asm volatile("cp.async.wait_group 0;");
        __syncthreads();
    }
    #undef ISSUE_X
    #undef LDG_A
    #undef STS_A

    // ---- epilogue ----
    const float* Sub = Subbase + (size_t)b*NN*FP;
    #pragma unroll
    for (int j=0;j<9;j++){
        const int row = rowBase + warp*16 + gid;
        const int col = j*8 + tig*2;
        float2 v0 = make_float2(acc[j][0], acc[j][1]);
        float2 v1 = make_float2(acc[j][2], acc[j][3]);
        if (combo){
            const float2 s0  = *(const float2*)(Sub + (size_t)row*FP + col);
            const float2 s1v = *(const float2*)(Sub + (size_t)(row+8)*FP + col);
            v0.x = 2.f*v0.x - s0.x;  v0.y = 2.f*v0.y - s0.y;
            v1.x = 2.f*v1.x - s1v.x; v1.y = 2.f*v1.y - s1v.y;
        }
        *(float2*)(Out + (size_t)row*FP + col)     = v0;
        *(float2*)(Out + (size_t)(row+8)*FP + col) = v1;
    }
}

// ---------------- gate ----------------
__global__ __launch_bounds__(256)
void gate_kernel(const float* __restrict__ gate_w, const float* __restrict__ gate_b,
                 const float* __restrict__ xt, const float* __restrict__ s1, const float* __restrict__ s2)
{
    __shared__ __align__(16) float Ws[6336];   // 66*96, reused as zbuf[64*96]
    __shared__ float xs[72][66];               // [k][node]
    const int tid = threadIdx.x;
    const int tx = tid & 31, ty = tid >> 5;
    const int nodeBase = blockIdx.x*64;

    unsigned long long acc[2][6];
    #pragma unroll
    for (int i=0;i<2;i++)
        #pragma unroll
        for (int j=0;j<6;j++) acc[i][j]=0ull;

    const float* srcs[6] = { g_X, g_T1, g_T2, g_X, g_T1 + (size_t)NODES*FP, g_T2 + (size_t)NODES*FP };

    for (int t=0;t<6;t++){
        __syncthreads();
        for (int i = tid*4; i < 6336; i += 1024)
            *(float4*)&Ws[i] = *(const float4*)&gate_w[t*6336 + i];
        const float* src = srcs[t] + (size_t)nodeBase*FP;
        for (int i = tid; i < 64*18; i += 256){
            const int n = i/18, q = i - n*18;
            const float4 v = *(const float4*)&src[(size_t)n*FP + q*4];
            xs[q*4+0][n]=v.x; xs[q*4+1][n]=v.y; xs[q*4+2][n]=v.z; xs[q*4+3][n]=v.w;
        }
        __syncthreads();
        for (int k=0;k<66;k++){
            const float4 w0 = *(const float4*)&Ws[k*96 + ty*12];
            const float4 w1 = *(const float4*)&Ws[k*96 + ty*12 + 4];
            const float4 w2 = *(const float4*)&Ws[k*96 + ty*12 + 8];
            const float2 xv = *(const float2*)&xs[k][tx*2];
            const unsigned long long xd0 = pk2(xv.x,xv.x), xd1 = pk2(xv.y,xv.y);
            const unsigned long long wp[6] = { pk2(w0.x,w0.y), pk2(w0.z,w0.w),
                                               pk2(w1.x,w1.y), pk2(w1.z,w1.w),
                                               pk2(w2.x,w2.y), pk2(w2.z,w2.w) };
            #pragma unroll
            for (int j=0;j<6;j++){
                fma2(acc[0][j], xd0, wp[j]);
                fma2(acc[1][j], xd1, wp[j]);
            }
        }
    }
    __syncthreads();
    float* zbuf = Ws;
    #pragma unroll
    for (int i=0;i<2;i++){
        const int n = tx*2 + i;
        #pragma unroll
        for (int j=0;j<6;j++){
            const float2 p = upk2(acc[i][j]);
            const int col = ty*12 + 2*j;
            zbuf[n*96 + col]   = sigmoidf_(p.x + gate_b[col]);
            zbuf[n*96 + col+1] = sigmoidf_(p.y + gate_b[col+1]);
        }
    }
    __syncthreads();
    for (int i = tid; i < 64*32; i += 256){
        const int n = i >> 5, o = i & 31;
        const int node = nodeBase + n;
        const float z1 = zbuf[n*96+o], z2 = zbuf[n*96+32+o], rr = zbuf[n*96+64+o];
        g_C[(size_t)node*FP + 2 + o]  = z1 * s1[node*32+o];
        g_C[(size_t)node*FP + 34 + o] = z2 * s2[node*32+o];
        g_r[node*32+o] = rr;
    }
    if (tid < 64){
        const int node = nodeBase + tid;
        g_C[(size_t)node*FP + 0] = xt[node*2+0];
        g_C[(size_t)node*FP + 1] = xt[node*2+1];
        #pragma unroll
        for (int p=66;p<FP;p++) g_C[(size_t)node*FP + p] = 0.f;
    }
}

// ---------------- final ----------------
__global__ __launch_bounds__(256)
void final_kernel(const float* __restrict__ upd_w, const float* __restrict__ upd_b,
                  const float* __restrict__ hop_w, const float* __restrict__ hop_b,
                  float* __restrict__ out)
{
    __shared__ __align__(16) float Ws[2112];   // 66*32
    __shared__ float xs[72][66];
    __shared__ float hbuf[64][33];
    __shared__ float hw[1024];
    const int tid = threadIdx.x;
    const int tx = tid & 31, ty = tid >> 5;
    const int nodeBase = blockIdx.x*64;

    unsigned long long acc[2][2];
    acc[0][0]=acc[0][1]=acc[1][0]=acc[1][1]=0ull;

    const float* srcs[6] = { g_C, g_U1, g_U2, g_C, g_U1 + (size_t)NODES*FP, g_U2 + (size_t)NODES*FP };

    for (int t=0;t<6;t++){
        __syncthreads();
        for (int i = tid*4; i < 2112; i += 1024)
            *(float4*)&Ws[i] = *(const float4*)&upd_w[t*2112 + i];
        const float* src = srcs[t] + (size_t)nodeBase*FP;
        for (int i = tid; i < 64*18; i += 256){
            const int n = i/18, q = i - n*18;
            const float4 v = *(const float4*)&src[(size_t)n*FP + q*4];
            xs[q*4+0][n]=v.x; xs[q*4+1][n]=v.y; xs[q*4+2][n]=v.z; xs[q*4+3][n]=v.w;
        }
        __syncthreads();
        for (int k=0;k<66;k++){
            const float4 w = *(const float4*)&Ws[k*32 + ty*4];
            const float2 xv = *(const float2*)&xs[k][tx*2];
            const unsigned long long xd0 = pk2(xv.x,xv.x), xd1 = pk2(xv.y,xv.y);
            const unsigned long long w0 = pk2(w.x,w.y), w1 = pk2(w.z,w.w);
            fma2(acc[0][0], xd0, w0); fma2(acc[0][1], xd0, w1);
            fma2(acc[1][0], xd1, w0); fma2(acc[1][1], xd1, w1);
        }
    }

    #pragma unroll
    for (int i=0;i<2;i++){
        const int n = tx*2 + i, node = nodeBase + n;
        #pragma unroll
        for (int j=0;j<2;j++){
            const float2 p = upk2(acc[i][j]);
            #pragma unroll
            for (int q=0;q<2;q++){
                const int col = ty*4 + 2*j + q;
                const float hc = tanhf((q ? p.y : p.x) + upd_b[col]);
                const float rr = g_r[node*32+col];
                const float st = g_state[node*32+col];
                const float h = rr*st + (1.f-rr)*hc;
                hbuf[n][col] = h;
                out[(size_t)node*32 + col] = h;
            }
        }
    }
    for (int i = tid; i < 1024; i += 256) hw[i] = hop_w[i];
    __syncthreads();
    for (int i = tid; i < 64*32; i += 256){
        const int n = i >> 5, o = i & 31;
        float a = hop_b[o];
        #pragma unroll
        for (int j=0;j<32;j++) a += hbuf[n][j]*hw[j*32+o];
        out[(size_t)NODES*32 + (size_t)(nodeBase+n)*32 + o] = a;
    }
}

// ---------------- launch ----------------
extern "C" void kernel_launch(void* const* d_in, const int* in_sizes, int n_in,
                              void* d_out, int out_size)
{
    (void)in_sizes; (void)n_in; (void)out_size;
    const float* xt       = (const float*)d_in[0];
    const float* s1       = (const float*)d_in[1];
    const float* s2       = (const float*)d_in[2];
    const float* ge       = (const float*)d_in[3];
    const float* supports = (const float*)d_in[4];
    const float* mlp_w    = (const float*)d_in[5];
    const float* mlp_b    = (const float*)d_in[6];
    const float* gate_w   = (const float*)d_in[7];
    const float* gate_b   = (const float*)d_in[8];
    const float* upd_w    = (const float*)d_in[9];
    const float* upd_b    = (const float*)d_in[10];
    const float* hop_w    = (const float*)d_in[11];
    const float* hop_b    = (const float*)d_in[12];
    float* out = (float*)d_out;

    float *pX, *pC, *pT1, *pT2, *pU1, *pU2;
    cudaGetSymbolAddress((void**)&pX,  g_X);
    cudaGetSymbolAddress((void**)&pC,  g_C);
    cudaGetSymbolAddress((void**)&pT1, g_T1);
    cudaGetSymbolAddress((void**)&pT2, g_T2);
    cudaGetSymbolAddress((void**)&pU1, g_U1);
    cudaGetSymbolAddress((void**)&pU2, g_U2);

    const int SMEM_BYTES = 2 * STAGE_E * 2;   // 104960
    cudaFuncSetAttribute(mma_gemm4, cudaFuncAttributeMaxDynamicSharedMemorySize, SMEM_BYTES);

    setup_kernel<<<NODES/128, 128>>>(xt, s1, s2, ge, mlp_w, mlp_b);
    splitT_kernel<<<dim3(NN/64, BB), 256>>>(pX);

    dim3 gg(NN/BM, BB, 2);
    mma_gemm4<<<gg, 512, SMEM_BYTES>>>(supports, pT1, pX, 0, 0);   // T1 = A @ X
    splitT_kernel<<<dim3(NN/64, 16), 256>>>(pT1);
    mma_gemm4<<<gg, 512, SMEM_BYTES>>>(supports, pT2, pX, 1, 1);   // T2 = 2A@T1 - X
    gate_kernel<<<NODES/64, 256>>>(gate_w, gate_b, xt, s1, s2);
    splitT_kernel<<<dim3(NN/64, BB), 256>>>(pC);
    mma_gemm4<<<gg, 512, SMEM_BYTES>>>(supports, pU1, pC, 0, 0);   // U1 = A @ C
    splitT_kernel<<<dim3(NN/64, 16), 256>>>(pU1);
    mma_gemm4<<<gg, 512, SMEM_BYTES>>>(supports, pU2, pC, 1, 1);   // U2 = 2A@U1 - C
    final_kernel<<<NODES/64, 256>>>(upd_w, upd_b, hop_w, hop_b, out);
}

// round 11
// speedup vs baseline: 1.3598x; 1.3598x over previous
#include <cuda_runtime.h>
#include <cuda_bf16.h>
#include <cstddef>

#define BB 8
#define NN 2048
#define NODES (BB*NN)          // 16384
#define FP 72                  // padded feature width (66 real)
#define DSZ 32
#define BM 128
#define BK 32
#define NT (NN/BK)             // 64 k-tiles
#define STAGE_E 16000          // bf16 elems per pipeline stage
#define NSTAGE 3

// ---------------- scratch (device globals, no allocation) ----------------
__device__ float g_X[NODES*FP];
__device__ float g_C[NODES*FP];
__device__ float g_state[NODES*DSZ];
__device__ float g_r[NODES*DSZ];
__device__ float g_T1[2*NODES*FP];
__device__ float g_T2[2*NODES*FP];
__device__ float g_U1[2*NODES*FP];
__device__ float g_U2[2*NODES*FP];

// pre-split A planes (bf16 hi/lo)
__device__ __align__(16) __nv_bfloat16 g_Ah[16ull*NN*NN];
__device__ __align__(16) __nv_bfloat16 g_Al[16ull*NN*NN];
// transposed/split dense-input planes [plane][72][2048]
__device__ __align__(16) __nv_bfloat16 g_InTh[16ull*FP*NN];
__device__ __align__(16) __nv_bfloat16 g_InTl[16ull*FP*NN];

// ---------------- helpers ----------------
__device__ __forceinline__ unsigned long long pk2(float lo, float hi){
    unsigned long long r;
    asm("mov.b64 %0, {%1,%2};" : "=l"(r) : "f"(lo), "f"(hi));
    return r;
}
__device__ __forceinline__ void fma2(unsigned long long &d, unsigned long long a, unsigned long long b){
    asm("fma.rn.f32x2 %0, %1, %2, %0;" : "+l"(d) : "l"(a), "l"(b));
}
__device__ __forceinline__ float2 upk2(unsigned long long v){
    float lo, hi;
    asm("mov.b64 {%0,%1}, %2;" : "=f"(lo), "=f"(hi) : "l"(v));
    return make_float2(lo, hi);
}
__device__ __forceinline__ float sigmoidf_(float x){ return 1.f/(1.f+__expf(-x)); }

__device__ __forceinline__ void mma_bf16(float acc[4],
    unsigned a0, unsigned a1, unsigned a2, unsigned a3, unsigned b0, unsigned b1)
{
    asm volatile("mma.sync.aligned.m16n8k16.row.col.f32.bf16.bf16.f32 "
        "{%0,%1,%2,%3},{%4,%5,%6,%7},{%8,%9},{%0,%1,%2,%3};"
        : "+f"(acc[0]), "+f"(acc[1]), "+f"(acc[2]), "+f"(acc[3])
        : "r"(a0), "r"(a1), "r"(a2), "r"(a3), "r"(b0), "r"(b1));
}
__device__ __forceinline__ void ldsm4(unsigned r[4], unsigned addr){
    asm volatile("ldmatrix.sync.aligned.m8n8.x4.shared.b16 {%0,%1,%2,%3}, [%4];"
        : "=r"(r[0]), "=r"(r[1]), "=r"(r[2]), "=r"(r[3]) : "r"(addr));
}
__device__ __forceinline__ void cvsplit(float v, __nv_bfloat16 &h, __nv_bfloat16 &l){
    h = __float2bfloat16(v);
    l = __float2bfloat16(v - __bfloat162float(h));
}
__device__ __forceinline__ unsigned smem_u32(const void* p){
    unsigned a;
    asm("{ .reg .u64 t; cvta.to.shared.u64 t, %1; cvt.u32.u64 %0, t; }" : "=r"(a) : "l"(p));
    return a;
}

// ---------------- split A: fp32 -> bf16 hi/lo planes (8 floats/thread) ----------------
__global__ void splitA_kernel(const float* __restrict__ A)
{
    const size_t idx = ((size_t)blockIdx.x*256 + threadIdx.x)*2;   // float4 pair index
    const float4 v0 = ((const float4*)A)[idx];
    const float4 v1 = ((const float4*)A)[idx+1];
    uint4 ho, lo;
    __nv_bfloat162* hp = (__nv_bfloat162*)&ho;
    __nv_bfloat162* lp = (__nv_bfloat162*)&lo;
    __nv_bfloat16 h[8], l[8];
    cvsplit(v0.x,h[0],l[0]); cvsplit(v0.y,h[1],l[1]); cvsplit(v0.z,h[2],l[2]); cvsplit(v0.w,h[3],l[3]);
    cvsplit(v1.x,h[4],l[4]); cvsplit(v1.y,h[5],l[5]); cvsplit(v1.z,h[6],l[6]); cvsplit(v1.w,h[7],l[7]);
    #pragma unroll
    for (int i=0;i<4;i++){ hp[i] = __halves2bfloat162(h[2*i],h[2*i+1]); lp[i] = __halves2bfloat162(l[2*i],l[2*i+1]); }
    ((uint4*)g_Ah)[idx/2] = ho;
    ((uint4*)g_Al)[idx/2] = lo;
}

// ---------------- transpose+split dense input ----------------
__global__ __launch_bounds__(256)
void splitT_kernel(const float* __restrict__ in)
{
    __shared__ float xs[64][73];
    const int tid = threadIdx.x;
    const int p = blockIdx.y;
    const int nodeBase = blockIdx.x*64;
    const float* src = in + ((size_t)p*NN + nodeBase)*FP;
    for (int i = tid; i < 64*18; i += 256){
        const int n = i/18, q = i - n*18;
        const float4 v = *(const float4*)&src[(size_t)n*FP + q*4];
        xs[n][q*4+0]=v.x; xs[n][q*4+1]=v.y; xs[n][q*4+2]=v.z; xs[n][q*4+3]=v.w;
    }
    __syncthreads();
    __nv_bfloat16* oh = g_InTh + (size_t)p*FP*NN + nodeBase;
    __nv_bfloat16* ol = g_InTl + (size_t)p*FP*NN + nodeBase;
    for (int i = tid; i < FP*64; i += 256){
        const int k = i >> 6, n = i & 63;
        __nv_bfloat16 h,l; cvsplit(xs[n][k], h, l);
        oh[(size_t)k*NN + n] = h;
        ol[(size_t)k*NN + n] = l;
    }
}

// ---------------- setup: mr/state + padded X ----------------
__global__ void setup_kernel(const float* __restrict__ xt, const float* __restrict__ s1,
                             const float* __restrict__ s2, const float* __restrict__ ge,
                             const float* __restrict__ mlp_w, const float* __restrict__ mlp_b)
{
    __shared__ float w[74*32];
    __shared__ float wb[32];
    const int tid = threadIdx.x;
    for (int i = tid; i < 74*32; i += blockDim.x) w[i] = mlp_w[i];
    if (tid < 32) wb[tid] = mlp_b[tid];
    __syncthreads();

    const int node = blockIdx.x*blockDim.x + tid;

    float in[74];
    #pragma unroll
    for (int i=0;i<2;i++)  in[i]    = xt[node*2+i];
    #pragma unroll
    for (int i=0;i<32;i++) in[2+i]  = s1[node*32+i];
    #pragma unroll
    for (int i=0;i<32;i++) in[34+i] = s2[node*32+i];
    #pragma unroll
    for (int i=0;i<8;i++)  in[66+i] = ge[node*8+i];

    float acc[32];
    #pragma unroll
    for (int o=0;o<32;o++) acc[o] = wb[o];
    for (int i=0;i<74;i++){
        float v = in[i];
        #pragma unroll
        for (int o=0;o<32;o++) acc[o] += v * w[i*32+o];
    }
    #pragma unroll
    for (int o=0;o<32;o++){
        float mr = sigmoidf_(acc[o]);
        g_state[node*32+o] = mr*in[2+o] + (1.f-mr)*in[34+o];
    }

    float* X = g_X + (size_t)node*FP;
    X[0]=in[0]; X[1]=in[1];
    #pragma unroll
    for (int i=0;i<32;i++){ X[2+i]=in[2+i]; X[34+i]=in[34+i]; }
    #pragma unroll
    for (int i=66;i<FP;i++) X[i]=0.f;
}

// ---------------- big GEMM v5: 3-stage cp.async with 2-tile cover ----------------
// stage (bf16 elems): Ah[128][40]@0, Al@5120, Xh[72][40]@10240, Xl@13120 -> 16000
__global__ __launch_bounds__(256, 2)
void mma_gemm5(float* __restrict__ Outbase, const float* __restrict__ Subbase,
               int inPerSupport, int combo)
{
    extern __shared__ __align__(16) __nv_bfloat16 sm2[];
    const unsigned smBase = smem_u32(sm2);

    const int b = blockIdx.y, s = blockIdx.z;
    const int sb = s*BB + b;
    const int ip = inPerSupport ? sb : b;
    const __nv_bfloat16* Ah_g = g_Ah + (size_t)sb*NN*NN;
    const __nv_bfloat16* Al_g = g_Al + (size_t)sb*NN*NN;
    const __nv_bfloat16* Xh_g = g_InTh + (size_t)ip*FP*NN;
    const __nv_bfloat16* Xl_g = g_InTl + (size_t)ip*FP*NN;
    float* Out = Outbase + (size_t)sb*NN*FP;

    const int tid = threadIdx.x;
    const int warp = tid >> 5, lane = tid & 31;
    const int gid = lane >> 2, tig = lane & 3;
    const int rowBase = blockIdx.x * BM;

    // ---- cp.async chunk map (1600 16B-chunks per stage) ----
    const __nv_bfloat16* pSrc[7];
    unsigned dOff[7];
    int nCh = 0;
    #pragma unroll
    for (int ii = 0; ii < 7; ii++){
        const int i = tid + ii*256;
        if (i < 1600){
            int c = i;
            const __nv_bfloat16* base; unsigned d;
            if (c < 512){ base = Ah_g; d = 0; }
            else if (c < 1024){ c -= 512; base = Al_g; d = 5120; }
            else if (c < 1312){ c -= 1024; base = Xh_g; d = 10240; }
            else { c -= 1312; base = Xl_g; d = 13120; }
            const int row = c >> 2, quad = c & 3;
            const size_t grow = (d < 10240) ? (size_t)(rowBase + row) : (size_t)row;
            pSrc[nCh] = base + grow*NN + quad*8;
            dOff[nCh] = d + row*40 + quad*8;
            nCh++;
        }
    }

    #define ISSUE_STAGE(SOFF, K0) do { \
        _Pragma("unroll") \
        for (int c = 0; c < 7; c++) if (c < nCh){ \
            const unsigned dst = smBase + ((SOFF) + dOff[c])*2; \
            const __nv_bfloat16* sp = pSrc[c] + (K0); \
            asm volatile("cp.async.cg.shared.global [%0], [%1], 16;" :: "r"(dst), "l"(sp)); \
        } \
        asm volatile("cp.async.commit_group;"); \
    } while(0)

    float acc[9][4];
    #pragma unroll
    for (int j=0;j<9;j++)
        #pragma unroll
        for (int q=0;q<4;q++) acc[j][q] = 0.f;

    const unsigned aStat = (unsigned)((warp*16 + ((lane>>3)&1)*8 + (lane&7))*40 + ((lane>>4)&1)*8);
    const unsigned bStat = (unsigned)((lane&7)*40 + (lane>>3)*8);

    // prologue: stages 0,1 in flight
    ISSUE_STAGE(0, 0);
    ISSUE_STAGE(STAGE_E, BK);

    for (int t = 0; t < NT; t++){
        const unsigned sOff = (unsigned)((t % NSTAGE) * STAGE_E);
        // stage t must be complete; stage t+1 may stay in flight (2-tile cover)
        if (t < NT-1) asm volatile("cp.async.wait_group 1;");
        else          asm volatile("cp.async.wait_group 0;");
        __syncthreads();
        if (t + 2 < NT) ISSUE_STAGE(((t+2) % NSTAGE) * STAGE_E, (t+2)*BK);

        // A fragments for this tile (both k16 halves, h+l)
        unsigned AH[2][4], AL[2][4];
        ldsm4(AH[0], smBase + (sOff + aStat)*2);
        ldsm4(AH[1], smBase + (sOff + aStat + 16)*2);
        ldsm4(AL[0], smBase + (sOff + 5120 + aStat)*2);
        ldsm4(AL[1], smBase + (sOff + 5120 + aStat + 16)*2);

        // B fragments ping-pong within the tile
        unsigned BH[2][4], BL[2][4];
        ldsm4(BH[0], smBase + (sOff + 10240 + bStat)*2);
        ldsm4(BL[0], smBase + (sOff + 13120 + bStat)*2);
        #pragma unroll
        for (int j=0;j<9;j++){
            const int pc = j & 1, pn = pc ^ 1;
            if (j < 8){
                ldsm4(BH[pn], smBase + (sOff + 10240 + (j+1)*320 + bStat)*2);
                ldsm4(BL[pn], smBase + (sOff + 13120 + (j+1)*320 + bStat)*2);
            }
            mma_bf16(acc[j], AH[0][0],AH[0][1],AH[0][2],AH[0][3], BH[pc][0],BH[pc][1]);
            mma_bf16(acc[j], AH[0][0],AH[0][1],AH[0][2],AH[0][3], BL[pc][0],BL[pc][1]);
            mma_bf16(acc[j], AL[0][0],AL[0][1],AL[0][2],AL[0][3], BH[pc][0],BH[pc][1]);
            mma_bf16(acc[j], AH[1][0],AH[1][1],AH[1][2],AH[1][3], BH[pc][2],BH[pc][3]);
            mma_bf16(acc[j], AH[1][0],AH[1][1],AH[1][2],AH[1][3], BL[pc][2],BL[pc][3]);
            mma_bf16(acc[j], AL[1][0],AL[1][1],AL[1][2],AL[1][3], BH[pc][2],BH[pc][3]);
        }
    }
    #undef ISSUE_STAGE

    // ---- epilogue ----
    const float* Sub = Subbase + (size_t)b*NN*FP;
    #pragma unroll
    for (int j=0;j<9;j++){
        const int row = rowBase + warp*16 + gid;
        const int col = j*8 + tig*2;
        float2 v0 = make_float2(acc[j][0], acc[j][1]);
        float2 v1 = make_float2(acc[j][2], acc[j][3]);
        if (combo){
            const float2 s0  = *(const float2*)(Sub + (size_t)row*FP + col);
            const float2 s1v = *(const float2*)(Sub + (size_t)(row+8)*FP + col);
            v0.x = 2.f*v0.x - s0.x;  v0.y = 2.f*v0.y - s0.y;
            v1.x = 2.f*v1.x - s1v.x; v1.y = 2.f*v1.y - s1v.y;
        }
        *(float2*)(Out + (size_t)row*FP + col)     = v0;
        *(float2*)(Out + (size_t)(row+8)*FP + col) = v1;
    }
}

// ---------------- gate ----------------
__global__ __launch_bounds__(256)
void gate_kernel(const float* __restrict__ gate_w, const float* __restrict__ gate_b,
                 const float* __restrict__ xt, const float* __restrict__ s1, const float* __restrict__ s2)
{
    __shared__ __align__(16) float Ws[6336];   // 66*96, reused as zbuf[64*96]
    __shared__ float xs[72][66];               // [k][node]
    const int tid = threadIdx.x;
    const int tx = tid & 31, ty = tid >> 5;
    const int nodeBase = blockIdx.x*64;

    unsigned long long acc[2][6];
    #pragma unroll
    for (int i=0;i<2;i++)
        #pragma unroll
        for (int j=0;j<6;j++) acc[i][j]=0ull;

    const float* srcs[6] = { g_X, g_T1, g_T2, g_X, g_T1 + (size_t)NODES*FP, g_T2 + (size_t)NODES*FP };

    for (int t=0;t<6;t++){
        __syncthreads();
        for (int i = tid*4; i < 6336; i += 1024)
            *(float4*)&Ws[i] = *(const float4*)&gate_w[t*6336 + i];
        const float* src = srcs[t] + (size_t)nodeBase*FP;
        for (int i = tid; i < 64*18; i += 256){
            const int n = i/18, q = i - n*18;
            const float4 v = *(const float4*)&src[(size_t)n*FP + q*4];
            xs[q*4+0][n]=v.x; xs[q*4+1][n]=v.y; xs[q*4+2][n]=v.z; xs[q*4+3][n]=v.w;
        }
        __syncthreads();
        for (int k=0;k<66;k++){
            const float4 w0 = *(const float4*)&Ws[k*96 + ty*12];
            const float4 w1 = *(const float4*)&Ws[k*96 + ty*12 + 4];
            const float4 w2 = *(const float4*)&Ws[k*96 + ty*12 + 8];
            const float2 xv = *(const float2*)&xs[k][tx*2];
            const unsigned long long xd0 = pk2(xv.x,xv.x), xd1 = pk2(xv.y,xv.y);
            const unsigned long long wp[6] = { pk2(w0.x,w0.y), pk2(w0.z,w0.w),
                                               pk2(w1.x,w1.y), pk2(w1.z,w1.w),
                                               pk2(w2.x,w2.y), pk2(w2.z,w2.w) };
            #pragma unroll
            for (int j=0;j<6;j++){
                fma2(acc[0][j], xd0, wp[j]);
                fma2(acc[1][j], xd1, wp[j]);
            }
        }
    }
    __syncthreads();
    float* zbuf = Ws;
    #pragma unroll
    for (int i=0;i<2;i++){
        const int n = tx*2 + i;
        #pragma unroll
        for (int j=0;j<6;j++){
            const float2 p = upk2(acc[i][j]);
            const int col = ty*12 + 2*j;
            zbuf[n*96 + col]   = sigmoidf_(p.x + gate_b[col]);
            zbuf[n*96 + col+1] = sigmoidf_(p.y + gate_b[col+1]);
        }
    }
    __syncthreads();
    for (int i = tid; i < 64*32; i += 256){
        const int n = i >> 5, o = i & 31;
        const int node = nodeBase + n;
        const float z1 = zbuf[n*96+o], z2 = zbuf[n*96+32+o], rr = zbuf[n*96+64+o];
        g_C[(size_t)node*FP + 2 + o]  = z1 * s1[node*32+o];
        g_C[(size_t)node*FP + 34 + o] = z2 * s2[node*32+o];
        g_r[node*32+o] = rr;
    }
    if (tid < 64){
        const int node = nodeBase + tid;
        g_C[(size_t)node*FP + 0] = xt[node*2+0];
        g_C[(size_t)node*FP + 1] = xt[node*2+1];
        #pragma unroll
        for (int p=66;p<FP;p++) g_C[(size_t)node*FP + p] = 0.f;
    }
}

// ---------------- final ----------------
__global__ __launch_bounds__(256)
void final_kernel(const float* __restrict__ upd_w, const float* __restrict__ upd_b,
                  const float* __restrict__ hop_w, const float* __restrict__ hop_b,
                  float* __restrict__ out)
{
    __shared__ __align__(16) float Ws[2112];   // 66*32
    __shared__ float xs[72][66];
    __shared__ float hbuf[64][33];
    __shared__ float hw[1024];
    const int tid = threadIdx.x;
    const int tx = tid & 31, ty = tid >> 5;
    const int nodeBase = blockIdx.x*64;

    unsigned long long acc[2][2];
    acc[0][0]=acc[0][1]=acc[1][0]=acc[1][1]=0ull;

    const float* srcs[6] = { g_C, g_U1, g_U2, g_C, g_U1 + (size_t)NODES*FP, g_U2 + (size_t)NODES*FP };

    for (int t=0;t<6;t++){
        __syncthreads();
        for (int i = tid*4; i < 2112; i += 1024)
            *(float4*)&Ws[i] = *(const float4*)&upd_w[t*2112 + i];
        const float* src = srcs[t] + (size_t)nodeBase*FP;
        for (int i = tid; i < 64*18; i += 256){
            const int n = i/18, q = i - n*18;
            const float4 v = *(const float4*)&src[(size_t)n*FP + q*4];
            xs[q*4+0][n]=v.x; xs[q*4+1][n]=v.y; xs[q*4+2][n]=v.z; xs[q*4+3][n]=v.w;
        }
        __syncthreads();
        for (int k=0;k<66;k++){
            const float4 w = *(const float4*)&Ws[k*32 + ty*4];
            const float2 xv = *(const float2*)&xs[k][tx*2];
            const unsigned long long xd0 = pk2(xv.x,xv.x), xd1 = pk2(xv.y,xv.y);
            const unsigned long long w0 = pk2(w.x,w.y), w1 = pk2(w.z,w.w);
            fma2(acc[0][0], xd0, w0); fma2(acc[0][1], xd0, w1);
            fma2(acc[1][0], xd1, w0); fma2(acc[1][1], xd1, w1);
        }
    }

    #pragma unroll
    for (int i=0;i<2;i++){
        const int n = tx*2 + i, node = nodeBase + n;
        #pragma unroll
        for (int j=0;j<2;j++){
            const float2 p = upk2(acc[i][j]);
            #pragma unroll
            for (int q=0;q<2;q++){
                const int col = ty*4 + 2*j + q;
                const float hc = tanhf((q ? p.y : p.x) + upd_b[col]);
                const float rr = g_r[node*32+col];
                const float st = g_state[node*32+col];
                const float h = rr*st + (1.f-rr)*hc;
                hbuf[n][col] = h;
                out[(size_t)node*32 + col] = h;
            }
        }
    }
    for (int i = tid; i < 1024; i += 256) hw[i] = hop_w[i];
    __syncthreads();
    for (int i = tid; i < 64*32; i += 256){
        const int n = i >> 5, o = i & 31;
        float a = hop_b[o];
        #pragma unroll
        for (int j=0;j<32;j++) a += hbuf[n][j]*hw[j*32+o];
        out[(size_t)NODES*32 + (size_t)(nodeBase+n)*32 + o] = a;
    }
}

// ---------------- launch ----------------
extern "C" void kernel_launch(void* const* d_in, const int* in_sizes, int n_in,
                              void* d_out, int out_size)
{
    (void)in_sizes; (void)n_in; (void)out_size;
    const float* xt       = (const float*)d_in[0];
    const float* s1       = (const float*)d_in[1];
    const float* s2       = (const float*)d_in[2];
    const float* ge       = (const float*)d_in[3];
    const float* supports = (const float*)d_in[4];
    const float* mlp_w    = (const float*)d_in[5];
    const float* mlp_b    = (const float*)d_in[6];
    const float* gate_w   = (const float*)d_in[7];
    const float* gate_b   = (const float*)d_in[8];
    const float* upd_w    = (const float*)d_in[9];
    const float* upd_b    = (const float*)d_in[10];
    const float* hop_w    = (const float*)d_in[11];
    const float* hop_b    = (const float*)d_in[12];
    float* out = (float*)d_out;

    float *pX, *pC, *pT1, *pT2, *pU1, *pU2;
    cudaGetSymbolAddress((void**)&pX,  g_X);
    cudaGetSymbolAddress((void**)&pC,  g_C);
    cudaGetSymbolAddress((void**)&pT1, g_T1);
    cudaGetSymbolAddress((void**)&pT2, g_T2);
    cudaGetSymbolAddress((void**)&pU1, g_U1);
    cudaGetSymbolAddress((void**)&pU2, g_U2);

    const int SMEM_BYTES = NSTAGE * STAGE_E * 2;   // 96000
    cudaFuncSetAttribute(mma_gemm5, cudaFuncAttributeMaxDynamicSharedMemorySize, SMEM_BYTES);

    setup_kernel<<<NODES/128, 128>>>(xt, s1, s2, ge, mlp_w, mlp_b);
    splitA_kernel<<<(16u*NN*NN)/8/256, 256>>>(supports);
    splitT_kernel<<<dim3(NN/64, BB), 256>>>(pX);

    dim3 gg(NN/BM, BB, 2);
    mma_gemm5<<<gg, 256, SMEM_BYTES>>>(pT1, pX, 0, 0);   // T1 = A @ X
    splitT_kernel<<<dim3(NN/64, 16), 256>>>(pT1);
    mma_gemm5<<<gg, 256, SMEM_BYTES>>>(pT2, pX, 1, 1);   // T2 = 2A@T1 - X
    gate_kernel<<<NODES/64, 256>>>(gate_w, gate_b, xt, s1, s2);
    splitT_kernel<<<dim3(NN/64, BB), 256>>>(pC);
    mma_gemm5<<<gg, 256, SMEM_BYTES>>>(pU1, pC, 0, 0);   // U1 = A @ C
    splitT_kernel<<<dim3(NN/64, 16), 256>>>(pU1);
    mma_gemm5<<<gg, 256, SMEM_BYTES>>>(pU2, pC, 1, 1);   // U2 = 2A@U1 - C
    final_kernel<<<NODES/64, 256>>>(upd_w, upd_b, hop_w, hop_b, out);
}

// round 14
// speedup vs baseline: 2.4124x; 1.7740x over previous
#include <cuda_runtime.h>
#include <cuda_fp16.h>
#include <cstddef>

#define BB 8
#define NN 2048
#define NODES (BB*NN)          // 16384
#define FP 72                  // padded feature width (66 real)
#define DSZ 32
#define BM 128
#define BK 32
#define NT (NN/BK)             // 64 k-tiles
#define STAGE_E 8000           // fp16 elems per stage: A 128*40 + X 72*40
#define NSTAGE 4

// ---------------- scratch (device globals, no allocation) ----------------
__device__ float g_X[NODES*FP];
__device__ float g_C[NODES*FP];
__device__ float g_state[NODES*DSZ];
__device__ float g_r[NODES*DSZ];
__device__ float g_T1[2*NODES*FP];
__device__ float g_T2[2*NODES*FP];
__device__ float g_U1[2*NODES*FP];
__device__ float g_U2[2*NODES*FP];

// fp16 A plane (134MB) and transposed fp16 dense-input planes [plane][72][2048]
__device__ __align__(16) __half g_Af[16ull*NN*NN];
__device__ __align__(16) __half g_InTf[16ull*FP*NN];

// ---------------- helpers ----------------
__device__ __forceinline__ unsigned long long pk2(float lo, float hi){
    unsigned long long r;
    asm("mov.b64 %0, {%1,%2};" : "=l"(r) : "f"(lo), "f"(hi));
    return r;
}
__device__ __forceinline__ void fma2(unsigned long long &d, unsigned long long a, unsigned long long b){
    asm("fma.rn.f32x2 %0, %1, %2, %0;" : "+l"(d) : "l"(a), "l"(b));
}
__device__ __forceinline__ float2 upk2(unsigned long long v){
    float lo, hi;
    asm("mov.b64 {%0,%1}, %2;" : "=f"(lo), "=f"(hi) : "l"(v));
    return make_float2(lo, hi);
}
__device__ __forceinline__ float sigmoidf_(float x){ return 1.f/(1.f+__expf(-x)); }

__device__ __forceinline__ void mma_f16(float acc[4],
    unsigned a0, unsigned a1, unsigned a2, unsigned a3, unsigned b0, unsigned b1)
{
    asm volatile("mma.sync.aligned.m16n8k16.row.col.f32.f16.f16.f32 "
        "{%0,%1,%2,%3},{%4,%5,%6,%7},{%8,%9},{%0,%1,%2,%3};"
        : "+f"(acc[0]), "+f"(acc[1]), "+f"(acc[2]), "+f"(acc[3])
        : "r"(a0), "r"(a1), "r"(a2), "r"(a3), "r"(b0), "r"(b1));
}
__device__ __forceinline__ void ldsm4(unsigned r[4], unsigned addr){
    asm volatile("ldmatrix.sync.aligned.m8n8.x4.shared.b16 {%0,%1,%2,%3}, [%4];"
        : "=r"(r[0]), "=r"(r[1]), "=r"(r[2]), "=r"(r[3]) : "r"(addr));
}
__device__ __forceinline__ unsigned smem_u32(const void* p){
    unsigned a;
    asm("{ .reg .u64 t; cvta.to.shared.u64 t, %1; cvt.u32.u64 %0, t; }" : "=r"(a) : "l"(p));
    return a;
}

// ---------------- convert A: fp32 -> fp16 plane (8 floats/thread) ----------------
__global__ void splitA_kernel(const float* __restrict__ A)
{
    const size_t idx = ((size_t)blockIdx.x*256 + threadIdx.x)*2;   // float4 pair index
    const float4 v0 = ((const float4*)A)[idx];
    const float4 v1 = ((const float4*)A)[idx+1];
    uint4 o;
    __half2* op = (__half2*)&o;
    op[0] = __floats2half2_rn(v0.x, v0.y);
    op[1] = __floats2half2_rn(v0.z, v0.w);
    op[2] = __floats2half2_rn(v1.x, v1.y);
    op[3] = __floats2half2_rn(v1.z, v1.w);
    ((uint4*)g_Af)[idx/2] = o;
}

// ---------------- transpose+convert dense input: [P][2048][72] fp32 -> [P][72][2048] fp16 ----
__global__ __launch_bounds__(256)
void splitT_kernel(const float* __restrict__ in)
{
    __shared__ float xs[64][73];
    const int tid = threadIdx.x;
    const int p = blockIdx.y;
    const int nodeBase = blockIdx.x*64;
    const float* src = in + ((size_t)p*NN + nodeBase)*FP;
    for (int i = tid; i < 64*18; i += 256){
        const int n = i/18, q = i - n*18;
        const float4 v = *(const float4*)&src[(size_t)n*FP + q*4];
        xs[n][q*4+0]=v.x; xs[n][q*4+1]=v.y; xs[n][q*4+2]=v.z; xs[n][q*4+3]=v.w;
    }
    __syncthreads();
    __half* of = g_InTf + (size_t)p*FP*NN + nodeBase;
    for (int i = tid; i < FP*64; i += 256){
        const int k = i >> 6, n = i & 63;
        of[(size_t)k*NN + n] = __float2half_rn(xs[n][k]);
    }
}

// ---------------- setup: mr/state + padded X ----------------
__global__ void setup_kernel(const float* __restrict__ xt, const float* __restrict__ s1,
                             const float* __restrict__ s2, const float* __restrict__ ge,
                             const float* __restrict__ mlp_w, const float* __restrict__ mlp_b)
{
    __shared__ float w[74*32];
    __shared__ float wb[32];
    const int tid = threadIdx.x;
    for (int i = tid; i < 74*32; i += blockDim.x) w[i] = mlp_w[i];
    if (tid < 32) wb[tid] = mlp_b[tid];
    __syncthreads();

    const int node = blockIdx.x*blockDim.x + tid;

    float in[74];
    #pragma unroll
    for (int i=0;i<2;i++)  in[i]    = xt[node*2+i];
    #pragma unroll
    for (int i=0;i<32;i++) in[2+i]  = s1[node*32+i];
    #pragma unroll
    for (int i=0;i<32;i++) in[34+i] = s2[node*32+i];
    #pragma unroll
    for (int i=0;i<8;i++)  in[66+i] = ge[node*8+i];

    float acc[32];
    #pragma unroll
    for (int o=0;o<32;o++) acc[o] = wb[o];
    for (int i=0;i<74;i++){
        float v = in[i];
        #pragma unroll
        for (int o=0;o<32;o++) acc[o] += v * w[i*32+o];
    }
    #pragma unroll
    for (int o=0;o<32;o++){
        float mr = sigmoidf_(acc[o]);
        g_state[node*32+o] = mr*in[2+o] + (1.f-mr)*in[34+o];
    }

    float* X = g_X + (size_t)node*FP;
    X[0]=in[0]; X[1]=in[1];
    #pragma unroll
    for (int i=0;i<32;i++){ X[2+i]=in[2+i]; X[34+i]=in[34+i]; }
    #pragma unroll
    for (int i=66;i<FP;i++) X[i]=0.f;
}

// ---------------- big GEMM v7: single-term fp16, 4-stage cp.async ----------------
// stage (fp16 elems): Af[128][40]@0, Xf[72][40]@5120 -> 8000
__global__ __launch_bounds__(256, 2)
void mma_gemm6(float* __restrict__ Outbase, const float* __restrict__ Subbase,
               int inPerSupport, int combo)
{
    extern __shared__ __align__(16) __half sm2[];
    const unsigned smBase = smem_u32(sm2);

    const int b = blockIdx.y, s = blockIdx.z;
    const int sb = s*BB + b;
    const int ip = inPerSupport ? sb : b;
    const __half* Af_g = g_Af + (size_t)sb*NN*NN;
    const __half* Xf_g = g_InTf + (size_t)ip*FP*NN;
    float* Out = Outbase + (size_t)sb*NN*FP;

    const int tid = threadIdx.x;
    const int warp = tid >> 5, lane = tid & 31;
    const int gid = lane >> 2, tig = lane & 3;
    const int rowBase = blockIdx.x * BM;

    // ---- cp.async chunk map (800 16B-chunks per stage) ----
    const __half* pSrc[4];
    unsigned dOff[4];
    int nCh = 0;
    #pragma unroll
    for (int ii = 0; ii < 4; ii++){
        const int i = tid + ii*256;
        if (i < 800){
            if (i < 512){
                const int row = i >> 2, quad = i & 3;
                pSrc[nCh] = Af_g + (size_t)(rowBase + row)*NN + quad*8;
                dOff[nCh] = row*40 + quad*8;
            } else {
                const int c = i - 512;
                const int row = c >> 2, quad = c & 3;
                pSrc[nCh] = Xf_g + (size_t)row*NN + quad*8;
                dOff[nCh] = 5120 + row*40 + quad*8;
            }
            nCh++;
        }
    }

    #define ISSUE_STAGE(SOFF, K0) do { \
        _Pragma("unroll") \
        for (int c = 0; c < 4; c++) if (c < nCh){ \
            const unsigned dst = smBase + ((SOFF) + dOff[c])*2; \
            const __half* sp = pSrc[c] + (K0); \
            asm volatile("cp.async.cg.shared.global [%0], [%1], 16;" :: "r"(dst), "l"(sp)); \
        } \
        asm volatile("cp.async.commit_group;"); \
    } while(0)

    float acc[9][4];
    #pragma unroll
    for (int j=0;j<9;j++)
        #pragma unroll
        for (int q=0;q<4;q++) acc[j][q] = 0.f;

    const unsigned aStat = (unsigned)((warp*16 + ((lane>>3)&1)*8 + (lane&7))*40 + ((lane>>4)&1)*8);
    const unsigned bStat = (unsigned)((lane&7)*40 + (lane>>3)*8);

    // prologue: stages 0,1,2 in flight
    ISSUE_STAGE(0, 0);
    ISSUE_STAGE(STAGE_E, BK);
    ISSUE_STAGE(2*STAGE_E, 2*BK);

    for (int t = 0; t < NT; t++){
        const unsigned sOff = (unsigned)((t % NSTAGE) * STAGE_E);
        if (t < NT-2)       asm volatile("cp.async.wait_group 2;");
        else if (t == NT-2) asm volatile("cp.async.wait_group 1;");
        else                asm volatile("cp.async.wait_group 0;");
        __syncthreads();
        if (t + 3 < NT) ISSUE_STAGE(((t+3) % NSTAGE) * STAGE_E, (t+3)*BK);

        // A fragments (both k16 halves)
        unsigned AF[2][4];
        ldsm4(AF[0], smBase + (sOff + aStat)*2);
        ldsm4(AF[1], smBase + (sOff + aStat + 16)*2);

        // B fragments ping-pong
        unsigned BF[2][4];
        ldsm4(BF[0], smBase + (sOff + 5120 + bStat)*2);
        #pragma unroll
        for (int j=0;j<9;j++){
            const int pc = j & 1, pn = pc ^ 1;
            if (j < 8)
                ldsm4(BF[pn], smBase + (sOff + 5120 + (j+1)*320 + bStat)*2);
            mma_f16(acc[j], AF[0][0],AF[0][1],AF[0][2],AF[0][3], BF[pc][0],BF[pc][1]);
            mma_f16(acc[j], AF[1][0],AF[1][1],AF[1][2],AF[1][3], BF[pc][2],BF[pc][3]);
        }
    }
    #undef ISSUE_STAGE

    // ---- epilogue ----
    const float* Sub = Subbase + (size_t)b*NN*FP;
    #pragma unroll
    for (int j=0;j<9;j++){
        const int row = rowBase + warp*16 + gid;
        const int col = j*8 + tig*2;
        float2 v0 = make_float2(acc[j][0], acc[j][1]);
        float2 v1 = make_float2(acc[j][2], acc[j][3]);
        if (combo){
            const float2 s0  = *(const float2*)(Sub + (size_t)row*FP + col);
            const float2 s1v = *(const float2*)(Sub + (size_t)(row+8)*FP + col);
            v0.x = 2.f*v0.x - s0.x;  v0.y = 2.f*v0.y - s0.y;
            v1.x = 2.f*v1.x - s1v.x; v1.y = 2.f*v1.y - s1v.y;
        }
        *(float2*)(Out + (size_t)row*FP + col)     = v0;
        *(float2*)(Out + (size_t)(row+8)*FP + col) = v1;
    }
}

// ---------------- gate ----------------
__global__ __launch_bounds__(256)
void gate_kernel(const float* __restrict__ gate_w, const float* __restrict__ gate_b,
                 const float* __restrict__ xt, const float* __restrict__ s1, const float* __restrict__ s2)
{
    __shared__ __align__(16) float Ws[6336];   // 66*96, reused as zbuf[64*96]
    __shared__ float xs[72][66];               // [k][node]
    const int tid = threadIdx.x;
    const int tx = tid & 31, ty = tid >> 5;
    const int nodeBase = blockIdx.x*64;

    unsigned long long acc[2][6];
    #pragma unroll
    for (int i=0;i<2;i++)
        #pragma unroll
        for (int j=0;j<6;j++) acc[i][j]=0ull;

    const float* srcs[6] = { g_X, g_T1, g_T2, g_X, g_T1 + (size_t)NODES*FP, g_T2 + (size_t)NODES*FP };

    for (int t=0;t<6;t++){
        __syncthreads();
        for (int i = tid*4; i < 6336; i += 1024)
            *(float4*)&Ws[i] = *(const float4*)&gate_w[t*6336 + i];
        const float* src = srcs[t] + (size_t)nodeBase*FP;
        for (int i = tid; i < 64*18; i += 256){
            const int n = i/18, q = i - n*18;
            const float4 v = *(const float4*)&src[(size_t)n*FP + q*4];
            xs[q*4+0][n]=v.x; xs[q*4+1][n]=v.y; xs[q*4+2][n]=v.z; xs[q*4+3][n]=v.w;
        }
        __syncthreads();
        for (int k=0;k<66;k++){
            const float4 w0 = *(const float4*)&Ws[k*96 + ty*12];
            const float4 w1 = *(const float4*)&Ws[k*96 + ty*12 + 4];
            const float4 w2 = *(const float4*)&Ws[k*96 + ty*12 + 8];
            const float2 xv = *(const float2*)&xs[k][tx*2];
            const unsigned long long xd0 = pk2(xv.x,xv.x), xd1 = pk2(xv.y,xv.y);
            const unsigned long long wp[6] = { pk2(w0.x,w0.y), pk2(w0.z,w0.w),
                                               pk2(w1.x,w1.y), pk2(w1.z,w1.w),
                                               pk2(w2.x,w2.y), pk2(w2.z,w2.w) };
            #pragma unroll
            for (int j=0;j<6;j++){
                fma2(acc[0][j], xd0, wp[j]);
                fma2(acc[1][j], xd1, wp[j]);
            }
        }
    }
    __syncthreads();
    float* zbuf = Ws;
    #pragma unroll
    for (int i=0;i<2;i++){
        const int n = tx*2 + i;
        #pragma unroll
        for (int j=0;j<6;j++){
            const float2 p = upk2(acc[i][j]);
            const int col = ty*12 + 2*j;
            zbuf[n*96 + col]   = sigmoidf_(p.x + gate_b[col]);
            zbuf[n*96 + col+1] = sigmoidf_(p.y + gate_b[col+1]);
        }
    }
    __syncthreads();
    for (int i = tid; i < 64*32; i += 256){
        const int n = i >> 5, o = i & 31;
        const int node = nodeBase + n;
        const float z1 = zbuf[n*96+o], z2 = zbuf[n*96+32+o], rr = zbuf[n*96+64+o];
        g_C[(size_t)node*FP + 2 + o]  = z1 * s1[node*32+o];
        g_C[(size_t)node*FP + 34 + o] = z2 * s2[node*32+o];
        g_r[node*32+o] = rr;
    }
    if (tid < 64){
        const int node = nodeBase + tid;
        g_C[(size_t)node*FP + 0] = xt[node*2+0];
        g_C[(size_t)node*FP + 1] = xt[node*2+1];
        #pragma unroll
        for (int p=66;p<FP;p++) g_C[(size_t)node*FP + p] = 0.f;
    }
}

// ---------------- final ----------------
__global__ __launch_bounds__(256)
void final_kernel(const float* __restrict__ upd_w, const float* __restrict__ upd_b,
                  const float* __restrict__ hop_w, const float* __restrict__ hop_b,
                  float* __restrict__ out)
{
    __shared__ __align__(16) float Ws[2112];   // 66*32
    __shared__ float xs[72][66];
    __shared__ float hbuf[64][33];
    __shared__ float hw[1024];
    const int tid = threadIdx.x;
    const int tx = tid & 31, ty = tid >> 5;
    const int nodeBase = blockIdx.x*64;

    unsigned long long acc[2][2];
    acc[0][0]=acc[0][1]=acc[1][0]=acc[1][1]=0ull;

    const float* srcs[6] = { g_C, g_U1, g_U2, g_C, g_U1 + (size_t)NODES*FP, g_U2 + (size_t)NODES*FP };

    for (int t=0;t<6;t++){
        __syncthreads();
        for (int i = tid*4; i < 2112; i += 1024)
            *(float4*)&Ws[i] = *(const float4*)&upd_w[t*2112 + i];
        const float* src = srcs[t] + (size_t)nodeBase*FP;
        for (int i = tid; i < 64*18; i += 256){
            const int n = i/18, q = i - n*18;
            const float4 v = *(const float4*)&src[(size_t)n*FP + q*4];
            xs[q*4+0][n]=v.x; xs[q*4+1][n]=v.y; xs[q*4+2][n]=v.z; xs[q*4+3][n]=v.w;
        }
        __syncthreads();
        for (int k=0;k<66;k++){
            const float4 w = *(const float4*)&Ws[k*32 + ty*4];
            const float2 xv = *(const float2*)&xs[k][tx*2];
            const unsigned long long xd0 = pk2(xv.x,xv.x), xd1 = pk2(xv.y,xv.y);
            const unsigned long long w0 = pk2(w.x,w.y), w1 = pk2(w.z,w.w);
            fma2(acc[0][0], xd0, w0); fma2(acc[0][1], xd0, w1);
            fma2(acc[1][0], xd1, w0); fma2(acc[1][1], xd1, w1);
        }
    }

    #pragma unroll
    for (int i=0;i<2;i++){
        const int n = tx*2 + i, node = nodeBase + n;
        #pragma unroll
        for (int j=0;j<2;j++){
            const float2 p = upk2(acc[i][j]);
            #pragma unroll
            for (int q=0;q<2;q++){
                const int col = ty*4 + 2*j + q;
                const float hc = tanhf((q ? p.y : p.x) + upd_b[col]);
                const float rr = g_r[node*32+col];
                const float st = g_state[node*32+col];
                const float h = rr*st + (1.f-rr)*hc;
                hbuf[n][col] = h;
                out[(size_t)node*32 + col] = h;
            }
        }
    }
    for (int i = tid; i < 1024; i += 256) hw[i] = hop_w[i];
    __syncthreads();
    for (int i = tid; i < 64*32; i += 256){
        const int n = i >> 5, o = i & 31;
        float a = hop_b[o];
        #pragma unroll
        for (int j=0;j<32;j++) a += hbuf[n][j]*hw[j*32+o];
        out[(size_t)NODES*32 + (size_t)(nodeBase+n)*32 + o] = a;
    }
}

// ---------------- launch ----------------
extern "C" void kernel_launch(void* const* d_in, const int* in_sizes, int n_in,
                              void* d_out, int out_size)
{
    (void)in_sizes; (void)n_in; (void)out_size;
    const float* xt       = (const float*)d_in[0];
    const float* s1       = (const float*)d_in[1];
    const float* s2       = (const float*)d_in[2];
    const float* ge       = (const float*)d_in[3];
    const float* supports = (const float*)d_in[4];
    const float* mlp_w    = (const float*)d_in[5];
    const float* mlp_b    = (const float*)d_in[6];
    const float* gate_w   = (const float*)d_in[7];
    const float* gate_b   = (const float*)d_in[8];
    const float* upd_w    = (const float*)d_in[9];
    const float* upd_b    = (const float*)d_in[10];
    const float* hop_w    = (const float*)d_in[11];
    const float* hop_b    = (const float*)d_in[12];
    float* out = (float*)d_out;

    float *pX, *pC, *pT1, *pT2, *pU1, *pU2;
    cudaGetSymbolAddress((void**)&pX,  g_X);
    cudaGetSymbolAddress((void**)&pC,  g_C);
    cudaGetSymbolAddress((void**)&pT1, g_T1);
    cudaGetSymbolAddress((void**)&pT2, g_T2);
    cudaGetSymbolAddress((void**)&pU1, g_U1);
    cudaGetSymbolAddress((void**)&pU2, g_U2);

    const int SMEM_BYTES = NSTAGE * STAGE_E * 2;   // 64000
    cudaFuncSetAttribute(mma_gemm6, cudaFuncAttributeMaxDynamicSharedMemorySize, SMEM_BYTES);

    setup_kernel<<<NODES/128, 128>>>(xt, s1, s2, ge, mlp_w, mlp_b);
    splitA_kernel<<<(16u*NN*NN)/8/256, 256>>>(supports);
    splitT_kernel<<<dim3(NN/64, BB), 256>>>(pX);

    dim3 gg(NN/BM, BB, 2);
    mma_gemm6<<<gg, 256, SMEM_BYTES>>>(pT1, pX, 0, 0);   // T1 = A @ X
    splitT_kernel<<<dim3(NN/64, 16), 256>>>(pT1);
    mma_gemm6<<<gg, 256, SMEM_BYTES>>>(pT2, pX, 1, 1);   // T2 = 2A@T1 - X
    gate_kernel<<<NODES/64, 256>>>(gate_w, gate_b, xt, s1, s2);
    splitT_kernel<<<dim3(NN/64, BB), 256>>>(pC);
    mma_gemm6<<<gg, 256, SMEM_BYTES>>>(pU1, pC, 0, 0);   // U1 = A @ C
    splitT_kernel<<<dim3(NN/64, 16), 256>>>(pU1);
    mma_gemm6<<<gg, 256, SMEM_BYTES>>>(pU2, pC, 1, 1);   // U2 = 2A@U1 - C
    final_kernel<<<NODES/64, 256>>>(upd_w, upd_b, hop_w, hop_b, out);
}